// round 14
// baseline (speedup 1.0000x reference)
#include <cuda_runtime.h>
#include <cstdint>

// Problem constants (fixed by the dataset)
#define BB 2
#define SS 2048
#define DD 1024
#define HH 16
#define DK 64
#define MM (BB * SS)  // 4096 rows

// Scratch (allocation-free rule: __device__ globals)
__device__ float g_q[(size_t)BB * HH * SS * DK];    // (B,H,S,DK) fp32
// K packed: per (bh, tile): 32 slots x 32 lanes x 16B {kh0,kh1,kl0,kl1} = 16KB
__device__ char g_kp[(size_t)BB * HH * 32 * 16384];
// V packed: per (bh, tile): 32 slots x 32 lanes x 8B {w0,w1} f16x2 = 8KB
__device__ char g_vp[(size_t)BB * HH * 32 * 8192];
// x packed (fp16 A-frag layout): per (mtile, ch): 8KB -> 32*32*8192 = 8MB
__device__ char g_xp[(size_t)32 * 32 * 8192];
// W packed (fp16 B-frag layout): per (z, ntile, ch): 8KB -> 4*8*32*8192 = 8MB
__device__ char g_wp[(size_t)4 * 8 * 32 * 8192];
// ctx packed (fp16 A-frag layout), written by attention epilogue
__device__ char g_cp[(size_t)32 * 32 * 8192];

// ---------------------------------------------------------------------------
// helpers (baseline sm_80+ ISA — no 'a'-suffix features)
// ---------------------------------------------------------------------------
__device__ __forceinline__ float ex2(float x) {
    float r;
    asm("ex2.approx.ftz.f32 %0, %1;" : "=f"(r) : "f"(x));
    return r;
}
__device__ __forceinline__ uint32_t pack_bf16x2(float lo, float hi) {
    uint32_t r;
    asm("cvt.rn.bf16x2.f32 %0, %1, %2;" : "=r"(r) : "f"(hi), "f"(lo));
    return r;
}
__device__ __forceinline__ uint32_t pack_f16x2(float lo, float hi) {
    uint32_t r;
    asm("cvt.rn.f16x2.f32 %0, %1, %2;" : "=r"(r) : "f"(hi), "f"(lo));
    return r;
}
__device__ __forceinline__ float bf16lo_f(uint32_t w) {
    return __uint_as_float(w << 16);
}
__device__ __forceinline__ float bf16hi_f(uint32_t w) {
    return __uint_as_float(w & 0xFFFF0000u);
}
__device__ __forceinline__ uint32_t smem_u32(const void* p) {
    uint32_t a;
    asm("{ .reg .u64 t; cvta.to.shared.u64 t, %1; cvt.u32.u64 %0, t; }"
        : "=r"(a) : "l"(p));
    return a;
}
__device__ __forceinline__ void cp16(uint32_t s, const void* g) {
    asm volatile("cp.async.cg.shared.global [%0], [%1], 16;"
                 :: "r"(s), "l"(g) : "memory");
}
#define CP_COMMIT() asm volatile("cp.async.commit_group;" ::: "memory")
#define CP_WAIT0()  asm volatile("cp.async.wait_group 0;" ::: "memory")

__device__ __forceinline__ void mma_bf16(float c[4], const uint32_t a[4],
                                         const uint32_t b[2]) {
    asm volatile(
        "mma.sync.aligned.m16n8k16.row.col.f32.bf16.bf16.f32 "
        "{%0,%1,%2,%3}, {%4,%5,%6,%7}, {%8,%9}, {%0,%1,%2,%3};"
        : "+f"(c[0]), "+f"(c[1]), "+f"(c[2]), "+f"(c[3])
        : "r"(a[0]), "r"(a[1]), "r"(a[2]), "r"(a[3]), "r"(b[0]), "r"(b[1]));
}
__device__ __forceinline__ void mma_fp16(float c[4], const uint32_t a[4],
                                         const uint32_t b[2]) {
    asm volatile(
        "mma.sync.aligned.m16n8k16.row.col.f32.f16.f16.f32 "
        "{%0,%1,%2,%3}, {%4,%5,%6,%7}, {%8,%9}, {%0,%1,%2,%3};"
        : "+f"(c[0]), "+f"(c[1]), "+f"(c[2]), "+f"(c[3])
        : "r"(a[0]), "r"(a[1]), "r"(a[2]), "r"(a[3]), "r"(b[0]), "r"(b[1]));
}

// ---------------------------------------------------------------------------
// Fragment-pack address helpers (formulas = the proven STORE_STAGE ones)
// A-layout chunk: 16 slots x 32 lanes x 16B; B-layout chunk: 32 x 32 x 8B
// ---------------------------------------------------------------------------
__device__ __forceinline__ void pack_A_pair(char* chunk, int row, int k4,
                                            uint32_t w0, uint32_t w1) {
    const int kt = k4 >> 2, p0 = (k4 & 3) * 2;
    const int rm = row & 15, mt = row >> 4;
    const int aidx = (rm >> 3) + ((p0 >> 2) << 1);
    const int slotA = kt * 8 + mt;
    const int lb = (rm & 7) * 4 + (p0 & 3);
    *(uint32_t*)(chunk + ((slotA * 32 + (lb ^ kt)) << 4) + (aidx << 2)) = w0;
    *(uint32_t*)(chunk + ((slotA * 32 + ((lb + 1) ^ kt)) << 4) + (aidx << 2)) = w1;
}
__device__ __forceinline__ void pack_B_pair(char* chunk, int row, int k4,
                                            uint32_t u0, uint32_t u1) {
    const int kt = k4 >> 2, p0 = (k4 & 3) * 2;
    const int rn = row & 7, nt = row >> 3;
    const int bidx = p0 >> 2;
    const int slotB = kt * 16 + nt;
    const int lb = rn * 4 + (p0 & 3);
    *(uint32_t*)(chunk + ((slotB * 32 + (lb ^ kt)) << 3) + (bidx << 2)) = u0;
    *(uint32_t*)(chunk + ((slotB * 32 + ((lb + 1) ^ kt)) << 3) + (bidx << 2)) = u1;
}

// ---------------------------------------------------------------------------
// Pack kernel: x -> g_xp (A-layout), Wq/Wk/Wv/Wo -> g_wp (B-layout)
// grid 8192 x 256; one float4 per thread.
// ---------------------------------------------------------------------------
__global__ void __launch_bounds__(256) pack_xw_kernel(
    const float* __restrict__ x,
    const float* __restrict__ Wq, const float* __restrict__ Wk,
    const float* __restrict__ Wv, const float* __restrict__ Wo) {
    const int gidx = blockIdx.x * 256 + threadIdx.x;
    if (blockIdx.x < 4096) {
        // x: 4096 rows x 256 float4
        const int row = gidx >> 8, f4 = gidx & 255;
        const int ch = f4 >> 3, k4 = f4 & 7;
        const float4 v = *(const float4*)(x + (size_t)row * DD + f4 * 4);
        char* chunk = g_xp + ((size_t)((row >> 7) * 32 + ch) << 13);
        pack_A_pair(chunk, row & 127, k4,
                    pack_f16x2(v.x, v.y), pack_f16x2(v.z, v.w));
    } else {
        const int wi = gidx - 4096 * 256;
        const int z = wi >> 18;                 // 262144 float4 per W
        const int r_ = wi & 262143;
        const float* W = (z == 0) ? Wq : (z == 1) ? Wk : (z == 2) ? Wv : Wo;
        const int row = r_ >> 8, f4 = r_ & 255;
        const int ch = f4 >> 3, k4 = f4 & 7;
        const float4 v = *(const float4*)(W + (size_t)row * DD + f4 * 4);
        char* chunk = g_wp + ((size_t)((z * 8 + (row >> 7)) * 32 + ch) << 13);
        pack_B_pair(chunk, row & 127, k4,
                    pack_f16x2(v.x, v.y), pack_f16x2(v.z, v.w));
    }
}

// ---------------------------------------------------------------------------
// K/V producer-side packing for attention (cloned from R11 STS code)
// ---------------------------------------------------------------------------
__device__ __forceinline__ void store_k_pair(int m, int cb, float f0, float f1) {
    const int b_ = m >> 11, s = m & 2047, h = cb >> 6, d = cb & 63;
    const int t = s >> 6, rw = s & 63;
    const int kt = d >> 4, dd = d & 15, quad = (dd >> 1) & 3, reg = dd >> 3;
    const int laneK = (((rw & 7) * 4) + quad) ^ kt;
    char* base = g_kp + ((size_t)((b_ * HH + h) * 32 + t) << 14) +
                 (((kt * 8 + (rw >> 3)) * 32 + laneK) << 4) + (reg << 2);
    const uint32_t kh = pack_bf16x2(f0, f1);
    const uint32_t kl = pack_bf16x2(f0 - bf16lo_f(kh), f1 - bf16hi_f(kh));
    *(uint32_t*)base = kh;
    *(uint32_t*)(base + 8) = kl;
}
__device__ __forceinline__ void store_v_pair(int m, int cb, float f0, float f1,
                                             float g0, float g1) {
    const int b_ = m >> 11, s = m & 2047, h = cb >> 6, d = cb & 63;
    const int t = s >> 6, kp = (s & 63) >> 1;
    const int kk = kp >> 3, kpb = kp & 7, word = kpb >> 2, tigv = kpb & 3;
    const int jv = d >> 3, gv = d & 7;
    char* tile = g_vp + ((size_t)((b_ * HH + h) * 32 + t) << 13);
    const uint32_t w0 = pack_f16x2(f0, g0);
    const uint32_t w1 = pack_f16x2(f1, g1);
    const int l0 = (4 * gv + tigv) ^ jv;
    const int l1 = (4 * (gv + 1) + tigv) ^ jv;
    *(uint32_t*)(tile + (((kk * 8 + jv) * 32 + l0) << 3) + (word << 2)) = w0;
    *(uint32_t*)(tile + (((kk * 8 + jv) * 32 + l1) << 3) + (word << 2)) = w1;
}

// ---------------------------------------------------------------------------
// fp16 mma.sync GEMM on PRE-PACKED operands: pure cp.async staging.
// MODE: 0 = plain row-major out, 1 = Q scatter fp32, 2 = K pack, 3 = V pack
// smem: 2 bufs x (A 8KB + B 8KB) = 32KB
// ---------------------------------------------------------------------------
#define MM_SMEM_BYTES 32768

template <int MODE>
__device__ __forceinline__ void mm_core(const char* __restrict__ Ap,
                                        const char* __restrict__ Bp,
                                        const float* __restrict__ bias,
                                        float* __restrict__ out,
                                        int m0, int n0) {
    extern __shared__ char smem[];
    const uint32_t sb = smem_u32(smem);
    const int tid = threadIdx.x;
    const int lane = tid & 31;
    const int wid = tid >> 5;
    const int warp_m = wid & 1;
    const int warp_n = wid >> 1;

    float c[4][4][4];
#pragma unroll
    for (int i = 0; i < 4; i++)
#pragma unroll
        for (int j = 0; j < 4; j++)
#pragma unroll
            for (int e = 0; e < 4; e++) c[i][j][e] = 0.0f;

    // prologue: stage chunk 0 into buf 0
    {
#pragma unroll
        for (int i = 0; i < 2; ++i) {
            cp16(sb + tid * 16 + i * 4096, Ap + tid * 16 + i * 4096);
            cp16(sb + 8192 + tid * 16 + i * 4096, Bp + tid * 16 + i * 4096);
        }
        CP_COMMIT();
    }

    for (int ch = 0; ch < 32; ++ch) {
        const int buf = ch & 1;
        CP_WAIT0();
        __syncthreads();
        if (ch + 1 < 32) {
            const uint32_t d = sb + (buf ^ 1) * 16384;
            const char* As = Ap + (size_t)(ch + 1) * 8192;
            const char* Bs = Bp + (size_t)(ch + 1) * 8192;
#pragma unroll
            for (int i = 0; i < 2; ++i) {
                cp16(d + tid * 16 + i * 4096, As + tid * 16 + i * 4096);
                cp16(d + 8192 + tid * 16 + i * 4096, Bs + tid * 16 + i * 4096);
            }
            CP_COMMIT();
        }

        const char* sbA = smem + buf * 16384;
        const char* sbB = sbA + 8192;
#pragma unroll
        for (int kt = 0; kt < 2; ++kt) {
            uint32_t af[4][4];
            uint32_t bf[4][2];
#pragma unroll
            for (int i = 0; i < 4; ++i) {
                const uint4 v = *(const uint4*)(sbA +
                    (((kt * 8 + warp_m * 4 + i) * 32 + (lane ^ kt)) << 4));
                af[i][0] = v.x; af[i][1] = v.y;
                af[i][2] = v.z; af[i][3] = v.w;
            }
#pragma unroll
            for (int j = 0; j < 4; ++j) {
                const uint2 v = *(const uint2*)(sbB +
                    (((kt * 16 + warp_n * 4 + j) * 32 + (lane ^ kt)) << 3));
                bf[j][0] = v.x; bf[j][1] = v.y;
            }
#pragma unroll
            for (int i = 0; i < 4; ++i)
#pragma unroll
                for (int j = 0; j < 4; ++j) mma_fp16(c[i][j], af[i], bf[j]);
        }
    }

#pragma unroll
    for (int i = 0; i < 4; ++i) {
        const int r0 = m0 + warp_m * 64 + i * 16 + (lane >> 2);
#pragma unroll
        for (int j = 0; j < 4; ++j) {
            const int cb = n0 + warp_n * 32 + j * 8 + 2 * (lane & 3);
            const float b0 = bias[cb], b1 = bias[cb + 1];
            float2 lo = {c[i][j][0] + b0, c[i][j][1] + b1};
            float2 hi = {c[i][j][2] + b0, c[i][j][3] + b1};
            if (MODE == 0) {
                *(float2*)(out + (size_t)r0 * DD + cb) = lo;
                *(float2*)(out + (size_t)(r0 + 8) * DD + cb) = hi;
            } else if (MODE == 1) {
                const int h = cb >> 6, d = cb & 63;
                const int bA = r0 >> 11, s0 = r0 & 2047;
                float* p0 = out + (((size_t)(bA * HH + h)) * SS + s0) * DK + d;
                *(float2*)p0 = lo;
                const int r1 = r0 + 8;
                const int bB = r1 >> 11, s1 = r1 & 2047;
                float* p1 = out + (((size_t)(bB * HH + h)) * SS + s1) * DK + d;
                *(float2*)p1 = hi;
            } else if (MODE == 2) {
                store_k_pair(r0, cb, lo.x, lo.y);
                store_k_pair(r0 + 8, cb, hi.x, hi.y);
            } else {
                const float p0x = __shfl_down_sync(0xFFFFFFFF, lo.x, 4);
                const float p0y = __shfl_down_sync(0xFFFFFFFF, lo.y, 4);
                const float p1x = __shfl_down_sync(0xFFFFFFFF, hi.x, 4);
                const float p1y = __shfl_down_sync(0xFFFFFFFF, hi.y, 4);
                if (((lane >> 2) & 1) == 0) {
                    store_v_pair(r0, cb, lo.x, lo.y, p0x, p0y);
                    store_v_pair(r0 + 8, cb, hi.x, hi.y, p1x, p1y);
                }
            }
        }
    }
}

__global__ void __launch_bounds__(256, 2) qkv_mm_kernel(
    const float* __restrict__ bq, const float* __restrict__ bk,
    const float* __restrict__ bv) {
    const int z = blockIdx.z;
    const int m0 = blockIdx.y * 128, n0 = blockIdx.x * 128;
    const char* Ap = g_xp + ((size_t)((m0 >> 7) * 32) << 13);
    const char* Bp = g_wp + ((size_t)((z * 8 + (n0 >> 7)) * 32) << 13);
    if (z == 0)
        mm_core<1>(Ap, Bp, bq, g_q, m0, n0);
    else if (z == 1)
        mm_core<2>(Ap, Bp, bk, nullptr, m0, n0);
    else
        mm_core<3>(Ap, Bp, bv, nullptr, m0, n0);
}

__global__ void __launch_bounds__(256, 2) oproj_mm_kernel(
    const float* __restrict__ bo, float* __restrict__ out) {
    const int m0 = blockIdx.y * 128, n0 = blockIdx.x * 128;
    const char* Ap = g_cp + ((size_t)((m0 >> 7) * 32) << 13);
    const char* Bp = g_wp + ((size_t)((3 * 8 + (n0 >> 7)) * 32) << 13);
    mm_core<0>(Ap, Bp, bo, out, m0, n0);
}

// ---------------------------------------------------------------------------
// Tensor-core flash attention (R13 mainloop; epilogue writes packed ctx).
// smem map (bytes): buf b at b*24576 {K 16KB, V 8KB}; mask at 49152+b*256
// ---------------------------------------------------------------------------
#define ATTN_SMEM 49664
#define A_BUFSTRIDE 24576
#define A_VOFF 16384
#define A_MSK 49152
#define QSCALE (0.125f * 1.44269504088896f)   // (1/sqrt(DK)) * log2(e)

__global__ void __launch_bounds__(256, 2) attn_kernel(const int* __restrict__ mask) {
    extern __shared__ char smem[];
    const uint32_t sb = smem_u32(smem);
    const int tid = threadIdx.x;
    const int lane = tid & 31;
    const int w = tid >> 5;
    const int gid = lane >> 2;
    const int tig = lane & 3;

    const int bh = blockIdx.y;
    const int b = bh >> 4;
    const int h = bh & 15;
    const int qs_base = blockIdx.x * 128 + w * 16;

    const float* qbase = g_q + (size_t)bh * SS * DK;
    const char* gkb = g_kp + ((size_t)bh << 19);
    const char* gvb = g_vp + ((size_t)bh << 18);

    // ---- Q fragments: bf16 hi/lo, m16n8k16 A layout, scale*log2e folded ----
    uint32_t qh[4][4], ql[4][4];
#pragma unroll
    for (int kt = 0; kt < 4; ++kt) {
#pragma unroll
        for (int r = 0; r < 4; ++r) {
            const int row = qs_base + gid + (r & 1) * 8;
            const int d = kt * 16 + 2 * tig + (r >> 1) * 8;
            const float2 qv = *(const float2*)(qbase + (size_t)row * DK + d);
            const float f0 = qv.x * QSCALE, f1 = qv.y * QSCALE;
            const uint32_t hw = pack_bf16x2(f0, f1);
            qh[kt][r] = hw;
            ql[kt][r] = pack_bf16x2(f0 - bf16lo_f(hw), f1 - bf16hi_f(hw));
        }
    }

    float o[8][4];
#pragma unroll
    for (int j = 0; j < 8; ++j)
#pragma unroll
        for (int e = 0; e < 4; ++e) o[j][e] = 0.0f;
    float m0 = -1e30f, m1 = -1e30f, l0 = 0.0f, l1 = 0.0f;

    // prologue: async-copy tile 0 into buf 0; prefetch mask
    {
#pragma unroll
        for (int i = 0; i < 4; ++i)
            cp16(sb + (tid + i * 256) * 16, gkb + (size_t)(tid + i * 256) * 16);
#pragma unroll
        for (int i = 0; i < 2; ++i)
            cp16(sb + A_VOFF + (tid + i * 256) * 16,
                 gvb + (size_t)(tid + i * 256) * 16);
        CP_COMMIT();
    }
    int rmask = 1;
    if (tid < 64) rmask = mask[b * SS + tid];

    for (int t = 0; t < SS / 64; ++t) {
        const int buf = t & 1;
        const char* kb = smem + buf * A_BUFSTRIDE;
        const char* vb = kb + A_VOFF;

        CP_WAIT0();
        if (tid < 64)
            *(float*)(smem + A_MSK + buf * 256 + tid * 4) = rmask ? 0.0f : -1e9f;
        if (t + 1 < SS / 64 && tid < 64)
            rmask = mask[b * SS + (t + 1) * 64 + tid];
        __syncthreads();

        if (t + 1 < SS / 64) {
            const uint32_t kd = sb + (buf ^ 1) * A_BUFSTRIDE;
            const char* gk = gkb + ((size_t)(t + 1) << 14);
#pragma unroll
            for (int i = 0; i < 4; ++i)
                cp16(kd + (tid + i * 256) * 16,
                     gk + (size_t)(tid + i * 256) * 16);
            const uint32_t vd = kd + A_VOFF;
            const char* gv = gvb + ((size_t)(t + 1) << 13);
#pragma unroll
            for (int i = 0; i < 2; ++i)
                cp16(vd + (tid + i * 256) * 16,
                     gv + (size_t)(tid + i * 256) * 16);
            CP_COMMIT();
        }

        // ---- scores (log2-domain): S = Q K^T via bf16 3-term ----
        float sc[8][4];
#pragma unroll
        for (int j = 0; j < 8; ++j)
#pragma unroll
            for (int e = 0; e < 4; ++e) sc[j][e] = 0.0f;
#pragma unroll
        for (int kt = 0; kt < 4; ++kt) {
#pragma unroll
            for (int j = 0; j < 8; ++j) {
                const uint4 k4v = *(const uint4*)(kb + (((kt * 8 + j) << 9) +
                                                       ((lane ^ kt) << 4)));
                uint32_t kh2[2] = {k4v.x, k4v.y};
                uint32_t kl2[2] = {k4v.z, k4v.w};
                mma_bf16(sc[j], qh[kt], kh2);
                mma_bf16(sc[j], qh[kt], kl2);
                mma_bf16(sc[j], ql[kt], kh2);
            }
        }

        // ---- mask, online softmax (log2-domain); overwrite sc with P ----
        const char* mbuf = smem + A_MSK + buf * 256;
#pragma unroll
        for (int j = 0; j < 8; ++j) {
            const float2 ma = *(const float2*)(mbuf + (j * 8 + 2 * tig) * 4);
            sc[j][0] += ma.x; sc[j][1] += ma.y;
            sc[j][2] += ma.x; sc[j][3] += ma.y;
        }
        float rm0 = -1e30f, rm1 = -1e30f;
#pragma unroll
        for (int j = 0; j < 8; ++j) {
            rm0 = fmaxf(rm0, fmaxf(sc[j][0], sc[j][1]));
            rm1 = fmaxf(rm1, fmaxf(sc[j][2], sc[j][3]));
        }
        rm0 = fmaxf(rm0, __shfl_xor_sync(0xFFFFFFFF, rm0, 1));
        rm0 = fmaxf(rm0, __shfl_xor_sync(0xFFFFFFFF, rm0, 2));
        rm1 = fmaxf(rm1, __shfl_xor_sync(0xFFFFFFFF, rm1, 1));
        rm1 = fmaxf(rm1, __shfl_xor_sync(0xFFFFFFFF, rm1, 2));
        const float nm0 = fmaxf(m0, rm0), nm1 = fmaxf(m1, rm1);
        const float c0 = ex2(m0 - nm0), c1 = ex2(m1 - nm1);
        m0 = nm0; m1 = nm1;
        l0 *= c0; l1 *= c1;
#pragma unroll
        for (int j = 0; j < 8; ++j) {
            o[j][0] *= c0; o[j][1] *= c0;
            o[j][2] *= c1; o[j][3] *= c1;
        }
        float s0 = 0.0f, s1 = 0.0f;
#pragma unroll
        for (int j = 0; j < 8; ++j) {
            const float p0 = ex2(sc[j][0] - nm0);
            const float p1 = ex2(sc[j][1] - nm0);
            const float p2 = ex2(sc[j][2] - nm1);
            const float p3 = ex2(sc[j][3] - nm1);
            s0 += p0 + p1; s1 += p2 + p3;
            sc[j][0] = p0; sc[j][1] = p1; sc[j][2] = p2; sc[j][3] = p3;
        }
        l0 += s0; l1 += s1;

        // ---- O += P V (fp16 k16; P direct from registers) ----
#pragma unroll
        for (int kk = 0; kk < 4; ++kk) {
            uint32_t pa[4];
            pa[0] = pack_f16x2(sc[2 * kk][0], sc[2 * kk][1]);
            pa[1] = pack_f16x2(sc[2 * kk][2], sc[2 * kk][3]);
            pa[2] = pack_f16x2(sc[2 * kk + 1][0], sc[2 * kk + 1][1]);
            pa[3] = pack_f16x2(sc[2 * kk + 1][2], sc[2 * kk + 1][3]);
#pragma unroll
            for (int j = 0; j < 8; ++j) {
                uint32_t bvf[2];
                const uint2 bv2 = *(const uint2*)(vb +
                    (((kk * 8 + j) * 32 + (lane ^ j)) << 3));
                bvf[0] = bv2.x; bvf[1] = bv2.y;
                mma_fp16(o[j], pa, bvf);
            }
        }
    }

    // ---- finalize: normalize and write ctx PRE-PACKED (fp16 A-frag) ----
    float lt0 = l0, lt1 = l1;
    lt0 += __shfl_xor_sync(0xFFFFFFFF, lt0, 1);
    lt0 += __shfl_xor_sync(0xFFFFFFFF, lt0, 2);
    lt1 += __shfl_xor_sync(0xFFFFFFFF, lt1, 1);
    lt1 += __shfl_xor_sync(0xFFFFFFFF, lt1, 2);
    const float inv0 = 1.0f / lt0, inv1 = 1.0f / lt1;

    const int mrow = b * SS + qs_base + gid;       // ctx row of r0
    const int mtile = mrow >> 7;
    const int r = mrow & 127;                      // r0 local; r1 = r + 8
#pragma unroll
    for (int j = 0; j < 8; ++j) {
        const int cG = h * DK + j * 8 + 2 * tig;   // global ctx column (even)
        const int ch = cG >> 5;
        const int k4 = (cG >> 2) & 7;
        const int pairhi = (cG >> 1) & 1;
        const int kt = k4 >> 2, p0 = (k4 & 3) * 2;
        char* chunk = g_cp + ((size_t)(mtile * 32 + ch) << 13);
        // row r0
        {
            const int rm = r & 15, mt = r >> 4;
            const int aidx = (rm >> 3) + ((p0 >> 2) << 1);
            const int slotA = kt * 8 + mt;
            const int lane_s = ((rm & 7) * 4 + (p0 & 3) + pairhi) ^ kt;
            *(uint32_t*)(chunk + ((slotA * 32 + lane_s) << 4) + (aidx << 2)) =
                pack_f16x2(o[j][0] * inv0, o[j][1] * inv0);
        }
        // row r1 = r + 8
        {
            const int r2 = r + 8;
            const int rm = r2 & 15, mt = r2 >> 4;
            const int aidx = (rm >> 3) + ((p0 >> 2) << 1);
            const int slotA = kt * 8 + mt;
            const int lane_s = ((rm & 7) * 4 + (p0 & 3) + pairhi) ^ kt;
            *(uint32_t*)(chunk + ((slotA * 32 + lane_s) << 4) + (aidx << 2)) =
                pack_f16x2(o[j][2] * inv1, o[j][3] * inv1);
        }
    }
}

// ---------------------------------------------------------------------------
// Inputs (metadata order): x, mask, Wq, bq, Wk, bk, Wv, bv, Wo, bo
// ---------------------------------------------------------------------------
extern "C" void kernel_launch(void* const* d_in, const int* in_sizes, int n_in,
                              void* d_out, int out_size) {
    const float* x  = (const float*)d_in[0];
    const int*   mk = (const int*)d_in[1];
    const float* Wq = (const float*)d_in[2];
    const float* bq = (const float*)d_in[3];
    const float* Wk = (const float*)d_in[4];
    const float* bk = (const float*)d_in[5];
    const float* Wv = (const float*)d_in[6];
    const float* bv = (const float*)d_in[7];
    const float* Wo = (const float*)d_in[8];
    const float* bo = (const float*)d_in[9];
    float* out = (float*)d_out;

    static bool configured = false;
    if (!configured) {
        cudaFuncSetAttribute(qkv_mm_kernel,
                             cudaFuncAttributeMaxDynamicSharedMemorySize,
                             MM_SMEM_BYTES);
        cudaFuncSetAttribute(oproj_mm_kernel,
                             cudaFuncAttributeMaxDynamicSharedMemorySize,
                             MM_SMEM_BYTES);
        cudaFuncSetAttribute(attn_kernel,
                             cudaFuncAttributeMaxDynamicSharedMemorySize,
                             ATTN_SMEM);
        configured = true;
    }

    // Pack x (A-frag) and all W (B-frag) once
    pack_xw_kernel<<<8192, 256>>>(x, Wq, Wk, Wv, Wo);

    // QKV projections from packed operands; K/V written attention-packed
    qkv_mm_kernel<<<dim3(DD / 128, MM / 128, 3), 256, MM_SMEM_BYTES>>>(
        bq, bk, bv);

    // Flash attention; writes ctx pre-packed for oproj
    attn_kernel<<<dim3(SS / 128, BB * HH), 256, ATTN_SMEM>>>(mk);

    // Output projection from packed ctx -> d_out
    oproj_mm_kernel<<<dim3(DD / 128, MM / 128), 256, MM_SMEM_BYTES>>>(bo, out);
}

// round 17
// speedup vs baseline: 1.4317x; 1.4317x over previous
#include <cuda_runtime.h>
#include <cstdint>

// Problem constants (fixed by the dataset)
#define BB 2
#define SS 2048
#define DD 1024
#define HH 16
#define DK 64
#define MM (BB * SS)  // 4096 rows

// Scratch (allocation-free rule: __device__ globals)
__device__ float g_q[(size_t)BB * HH * SS * DK];    // (B,H,S,DK) fp32
__device__ float g_ctx[(size_t)BB * SS * DD];       // (B,S,D)
// K packed (fp16 single): per (bh, tile): 32 slots x 32 lanes x 8B = 8KB
__device__ char g_kp[(size_t)BB * HH * 32 * 8192];
// V packed: per (bh, tile): 32 slots x 32 lanes x 8B {w0,w1} f16x2 = 8KB
__device__ char g_vp[(size_t)BB * HH * 32 * 8192];

// ---------------------------------------------------------------------------
// helpers (baseline sm_80+ ISA — no 'a'-suffix features)
// ---------------------------------------------------------------------------
__device__ __forceinline__ float ex2(float x) {
    float r;
    asm("ex2.approx.ftz.f32 %0, %1;" : "=f"(r) : "f"(x));
    return r;
}
__device__ __forceinline__ uint32_t pack_f16x2(float lo, float hi) {
    uint32_t r;
    asm("cvt.rn.f16x2.f32 %0, %1, %2;" : "=r"(r) : "f"(hi), "f"(lo));
    return r;
}
__device__ __forceinline__ float f16lo_f(uint32_t w) {
    float f;
    asm("{.reg .b16 l, h; mov.b32 {l, h}, %1; cvt.f32.f16 %0, l;}"
        : "=f"(f) : "r"(w));
    return f;
}
__device__ __forceinline__ float f16hi_f(uint32_t w) {
    float f;
    asm("{.reg .b16 l, h; mov.b32 {l, h}, %1; cvt.f32.f16 %0, h;}"
        : "=f"(f) : "r"(w));
    return f;
}
__device__ __forceinline__ uint32_t smem_u32(const void* p) {
    uint32_t a;
    asm("{ .reg .u64 t; cvta.to.shared.u64 t, %1; cvt.u32.u64 %0, t; }"
        : "=r"(a) : "l"(p));
    return a;
}
__device__ __forceinline__ void cp16(uint32_t s, const void* g) {
    asm volatile("cp.async.cg.shared.global [%0], [%1], 16;"
                 :: "r"(s), "l"(g) : "memory");
}
#define CP_COMMIT() asm volatile("cp.async.commit_group;" ::: "memory")
#define CP_WAIT0()  asm volatile("cp.async.wait_group 0;" ::: "memory")

__device__ __forceinline__ void mma_fp16(float c[4], const uint32_t a[4],
                                         const uint32_t b[2]) {
    asm volatile(
        "mma.sync.aligned.m16n8k16.row.col.f32.f16.f16.f32 "
        "{%0,%1,%2,%3}, {%4,%5,%6,%7}, {%8,%9}, {%0,%1,%2,%3};"
        : "+f"(c[0]), "+f"(c[1]), "+f"(c[2]), "+f"(c[3])
        : "r"(a[0]), "r"(a[1]), "r"(a[2]), "r"(a[3]), "r"(b[0]), "r"(b[1]));
}

// ---------------------------------------------------------------------------
// K/V producer-side packing for attention
// ---------------------------------------------------------------------------
__device__ __forceinline__ void store_k_pair(int m, int cb, float f0, float f1) {
    const int b_ = m >> 11, s = m & 2047, h = cb >> 6, d = cb & 63;
    const int t = s >> 6, rw = s & 63;
    const int kt = d >> 4, dd = d & 15, quad = (dd >> 1) & 3, reg = dd >> 3;
    const int laneK = (((rw & 7) * 4) + quad) ^ kt;
    char* base = g_kp + ((size_t)((b_ * HH + h) * 32 + t) << 13) +
                 (((kt * 8 + (rw >> 3)) * 32 + laneK) << 3) + (reg << 2);
    *(uint32_t*)base = pack_f16x2(f0, f1);
}
// m = even row; values f* for row m, g* for row m+1, at cols (cb, cb+1)
__device__ __forceinline__ void store_v_pair(int m, int cb, float f0, float f1,
                                             float g0, float g1) {
    const int b_ = m >> 11, s = m & 2047, h = cb >> 6, d = cb & 63;
    const int t = s >> 6, kp = (s & 63) >> 1;
    const int kk = kp >> 3, kpb = kp & 7, word = kpb >> 2, tigv = kpb & 3;
    const int jv = d >> 3, gv = d & 7;
    char* tile = g_vp + ((size_t)((b_ * HH + h) * 32 + t) << 13);
    const uint32_t w0 = pack_f16x2(f0, g0);
    const uint32_t w1 = pack_f16x2(f1, g1);
    const int l0 = (4 * gv + tigv) ^ jv;
    const int l1 = (4 * (gv + 1) + tigv) ^ jv;
    *(uint32_t*)(tile + (((kk * 8 + jv) * 32 + l0) << 3) + (word << 2)) = w0;
    *(uint32_t*)(tile + (((kk * 8 + jv) * 32 + l1) << 3) + (word << 2)) = w1;
}

// ---------------------------------------------------------------------------
// fp16 mma.sync GEMM: C[128,128] = A[128,1024] * W[128,1024]^T + bias
// MODE: 0 = plain row-major out, 1 = Q scatter fp32, 2 = K pack, 3 = V pack
// ---------------------------------------------------------------------------
#define MM_SMEM_BYTES 32768

template <int MODE>
__device__ __forceinline__ void mm_core(const float* __restrict__ A,
                                        const float* __restrict__ W,
                                        const float* __restrict__ bias,
                                        float* __restrict__ out,
                                        int m0, int n0) {
    extern __shared__ char smem[];
    const int tid = threadIdx.x;
    const int lane = tid & 31;
    const int wid = tid >> 5;
    const int warp_m = wid & 1;
    const int warp_n = wid >> 1;

    float c[4][4][4];
#pragma unroll
    for (int i = 0; i < 4; i++)
#pragma unroll
        for (int j = 0; j < 4; j++)
#pragma unroll
            for (int e = 0; e < 4; e++) c[i][j][e] = 0.0f;

    const float* Abase = A + (size_t)m0 * DD;
    const float* Wbase = W + (size_t)n0 * DD;

    float4 av[4], bv[4];

#define STORE_STAGE(bufp)                                                     \
    do {                                                                      \
        char* sbA = smem + (bufp) * 16384;                                    \
        char* sbB = sbA + 8192;                                               \
        _Pragma("unroll") for (int i = 0; i < 4; i++) {                       \
            const int idx = tid + i * 256;                                    \
            const int row = idx >> 3, k4 = idx & 7;                           \
            const int kt = k4 >> 2;                                           \
            const int p0 = (k4 & 3) * 2;                                      \
            const uint32_t w0 = pack_f16x2(av[i].x, av[i].y);                 \
            const uint32_t w1 = pack_f16x2(av[i].z, av[i].w);                 \
            const uint32_t u0 = pack_f16x2(bv[i].x, bv[i].y);                 \
            const uint32_t u1 = pack_f16x2(bv[i].z, bv[i].w);                 \
            { /* A pack */                                                    \
                const int rm = row & 15, mt = row >> 4;                       \
                const int aidx = (rm >> 3) + ((p0 >> 2) << 1);                \
                const int slotA = kt * 8 + mt;                                \
                const int lb = (rm & 7) * 4 + (p0 & 3);                       \
                *(uint32_t*)(sbA + ((slotA * 32 + (lb ^ kt)) << 4)            \
                             + (aidx << 2)) = w0;                             \
                *(uint32_t*)(sbA + ((slotA * 32 + ((lb + 1) ^ kt)) << 4)      \
                             + (aidx << 2)) = w1;                             \
            }                                                                 \
            { /* B pack */                                                    \
                const int rn = row & 7, nt = row >> 3;                        \
                const int bidx = p0 >> 2;                                     \
                const int slotB = kt * 16 + nt;                               \
                const int lb = rn * 4 + (p0 & 3);                             \
                *(uint32_t*)(sbB + ((slotB * 32 + (lb ^ kt)) << 3)            \
                             + (bidx << 2)) = u0;                             \
                *(uint32_t*)(sbB + ((slotB * 32 + ((lb + 1) ^ kt)) << 3)      \
                             + (bidx << 2)) = u1;                             \
            }                                                                 \
        }                                                                     \
    } while (0)

#define LOAD_STAGE(c0)                                                        \
    do {                                                                      \
        _Pragma("unroll") for (int i = 0; i < 4; i++) {                       \
            const int idx = tid + i * 256;                                    \
            const int row = idx >> 3, k4 = idx & 7;                           \
            av[i] = *(const float4*)(Abase + (size_t)row * DD + (c0) + k4 * 4); \
            bv[i] = *(const float4*)(Wbase + (size_t)row * DD + (c0) + k4 * 4); \
        }                                                                     \
    } while (0)

    LOAD_STAGE(0);

    for (int ch = 0; ch < 32; ++ch) {
        const int buf = ch & 1;
        STORE_STAGE(buf);
        if (ch + 1 < 32) LOAD_STAGE((ch + 1) * 32);
        __syncthreads();

        const char* sbA = smem + buf * 16384;
        const char* sbB = sbA + 8192;
#pragma unroll
        for (int kt = 0; kt < 2; ++kt) {
            uint32_t af[4][4];
            uint32_t bf[4][2];
#pragma unroll
            for (int i = 0; i < 4; ++i) {
                const uint4 v = *(const uint4*)(sbA +
                    (((kt * 8 + warp_m * 4 + i) * 32 + (lane ^ kt)) << 4));
                af[i][0] = v.x; af[i][1] = v.y;
                af[i][2] = v.z; af[i][3] = v.w;
            }
#pragma unroll
            for (int j = 0; j < 4; ++j) {
                const uint2 v = *(const uint2*)(sbB +
                    (((kt * 16 + warp_n * 4 + j) * 32 + (lane ^ kt)) << 3));
                bf[j][0] = v.x; bf[j][1] = v.y;
            }
#pragma unroll
            for (int i = 0; i < 4; ++i)
#pragma unroll
                for (int j = 0; j < 4; ++j) mma_fp16(c[i][j], af[i], bf[j]);
        }
    }

#pragma unroll
    for (int i = 0; i < 4; ++i) {
        const int r0 = m0 + warp_m * 64 + i * 16 + (lane >> 2);
#pragma unroll
        for (int j = 0; j < 4; ++j) {
            const int cb = n0 + warp_n * 32 + j * 8 + 2 * (lane & 3);
            const float b0 = bias[cb], b1 = bias[cb + 1];
            float2 lo = {c[i][j][0] + b0, c[i][j][1] + b1};
            float2 hi = {c[i][j][2] + b0, c[i][j][3] + b1};
            if (MODE == 0) {
                *(float2*)(out + (size_t)r0 * DD + cb) = lo;
                *(float2*)(out + (size_t)(r0 + 8) * DD + cb) = hi;
            } else if (MODE == 1) {
                const int h = cb >> 6, d = cb & 63;
                const int bA = r0 >> 11, s0 = r0 & 2047;
                float* p0 = out + (((size_t)(bA * HH + h)) * SS + s0) * DK + d;
                *(float2*)p0 = lo;
                const int r1 = r0 + 8;
                const int bB = r1 >> 11, s1 = r1 & 2047;
                float* p1 = out + (((size_t)(bB * HH + h)) * SS + s1) * DK + d;
                *(float2*)p1 = hi;
            } else if (MODE == 2) {
                store_k_pair(r0, cb, lo.x, lo.y);
                store_k_pair(r0 + 8, cb, hi.x, hi.y);
            } else {
                const float p0x = __shfl_down_sync(0xFFFFFFFF, lo.x, 4);
                const float p0y = __shfl_down_sync(0xFFFFFFFF, lo.y, 4);
                const float p1x = __shfl_down_sync(0xFFFFFFFF, hi.x, 4);
                const float p1y = __shfl_down_sync(0xFFFFFFFF, hi.y, 4);
                if (((lane >> 2) & 1) == 0) {
                    store_v_pair(r0, cb, lo.x, lo.y, p0x, p0y);
                    store_v_pair(r0 + 8, cb, hi.x, hi.y, p1x, p1y);
                }
            }
        }
    }
#undef STORE_STAGE
#undef LOAD_STAGE
}

__global__ void __launch_bounds__(256) qkv_mm_kernel(
    const float* __restrict__ x,
    const float* __restrict__ Wq, const float* __restrict__ bq,
    const float* __restrict__ Wk, const float* __restrict__ bk,
    const float* __restrict__ Wv, const float* __restrict__ bv) {
    const int z = blockIdx.z;
    const int m0 = blockIdx.y * 128, n0 = blockIdx.x * 128;
    if (z == 0)
        mm_core<1>(x, Wq, bq, g_q, m0, n0);
    else if (z == 1)
        mm_core<2>(x, Wk, bk, nullptr, m0, n0);
    else
        mm_core<3>(x, Wv, bv, nullptr, m0, n0);
}

__global__ void __launch_bounds__(256) oproj_mm_kernel(
    const float* __restrict__ Wo, const float* __restrict__ bo,
    float* __restrict__ out) {
    mm_core<0>(g_ctx, Wo, bo, out, blockIdx.y * 128, blockIdx.x * 128);
}

// ---------------------------------------------------------------------------
// Tensor-core flash attention, round 15:
//  - QK via fp16 Q-split 2-term (qh*k + ql*k), K single fp16: 64 QK mmas.
//  - PV fp16 k16 register-direct (unchanged). cp.async staging, 2 CTAs/SM.
//
// smem map (bytes): buf b at b*16384 {K 8KB, V 8KB}; mask at 32768+b*256
// ---------------------------------------------------------------------------
#define ATTN_SMEM 33280
#define A_BUFSTRIDE 16384
#define A_VOFF 8192
#define A_MSK 32768
#define QSCALE (0.125f * 1.44269504088896f)   // (1/sqrt(DK)) * log2(e)

__global__ void __launch_bounds__(256, 2) attn_kernel(const int* __restrict__ mask) {
    extern __shared__ char smem[];
    const uint32_t sb = smem_u32(smem);
    const int tid = threadIdx.x;
    const int lane = tid & 31;
    const int w = tid >> 5;
    const int gid = lane >> 2;
    const int tig = lane & 3;

    const int bh = blockIdx.y;
    const int b = bh >> 4;
    const int h = bh & 15;
    const int qs_base = blockIdx.x * 128 + w * 16;

    const float* qbase = g_q + (size_t)bh * SS * DK;
    const char* gkb = g_kp + ((size_t)bh << 18);
    const char* gvb = g_vp + ((size_t)bh << 18);

    // ---- Q fragments: fp16 hi/lo, m16n8k16 A layout, scale*log2e folded ----
    uint32_t qh[4][4], ql[4][4];
#pragma unroll
    for (int kt = 0; kt < 4; ++kt) {
#pragma unroll
        for (int r = 0; r < 4; ++r) {
            const int row = qs_base + gid + (r & 1) * 8;
            const int d = kt * 16 + 2 * tig + (r >> 1) * 8;
            const float2 qv = *(const float2*)(qbase + (size_t)row * DK + d);
            const float f0 = qv.x * QSCALE, f1 = qv.y * QSCALE;
            const uint32_t hw = pack_f16x2(f0, f1);
            qh[kt][r] = hw;
            ql[kt][r] = pack_f16x2(f0 - f16lo_f(hw), f1 - f16hi_f(hw));
        }
    }

    float o[8][4];
#pragma unroll
    for (int j = 0; j < 8; ++j)
#pragma unroll
        for (int e = 0; e < 4; ++e) o[j][e] = 0.0f;
    float m0 = -1e30f, m1 = -1e30f, l0 = 0.0f, l1 = 0.0f;

    // prologue: async-copy tile 0 into buf 0; prefetch mask
    {
#pragma unroll
        for (int i = 0; i < 2; ++i)
            cp16(sb + (tid + i * 256) * 16, gkb + (size_t)(tid + i * 256) * 16);
#pragma unroll
        for (int i = 0; i < 2; ++i)
            cp16(sb + A_VOFF + (tid + i * 256) * 16,
                 gvb + (size_t)(tid + i * 256) * 16);
        CP_COMMIT();
    }
    int rmask = 1;
    if (tid < 64) rmask = mask[b * SS + tid];

    for (int t = 0; t < SS / 64; ++t) {
        const int buf = t & 1;
        const char* kb = smem + buf * A_BUFSTRIDE;
        const char* vb = kb + A_VOFF;

        CP_WAIT0();
        if (tid < 64)
            *(float*)(smem + A_MSK + buf * 256 + tid * 4) = rmask ? 0.0f : -1e9f;
        if (t + 1 < SS / 64 && tid < 64)
            rmask = mask[b * SS + (t + 1) * 64 + tid];
        __syncthreads();

        // issue copy of tile t+1 (safe: all warps are past compute(t-1))
        if (t + 1 < SS / 64) {
            const uint32_t kd = sb + (buf ^ 1) * A_BUFSTRIDE;
            const char* gk = gkb + ((size_t)(t + 1) << 13);
#pragma unroll
            for (int i = 0; i < 2; ++i)
                cp16(kd + (tid + i * 256) * 16,
                     gk + (size_t)(tid + i * 256) * 16);
            const uint32_t vd = kd + A_VOFF;
            const char* gv = gvb + ((size_t)(t + 1) << 13);
#pragma unroll
            for (int i = 0; i < 2; ++i)
                cp16(vd + (tid + i * 256) * 16,
                     gv + (size_t)(tid + i * 256) * 16);
            CP_COMMIT();
        }

        // ---- scores (log2-domain): S = Q K^T via fp16 2-term ----
        float sc[8][4];
#pragma unroll
        for (int j = 0; j < 8; ++j)
#pragma unroll
            for (int e = 0; e < 4; ++e) sc[j][e] = 0.0f;
#pragma unroll
        for (int kt = 0; kt < 4; ++kt) {
#pragma unroll
            for (int j = 0; j < 8; ++j) {
                const uint2 kv = *(const uint2*)(kb + (((kt * 8 + j) << 8) +
                                                      ((lane ^ kt) << 3)));
                uint32_t kh2[2] = {kv.x, kv.y};
                mma_fp16(sc[j], qh[kt], kh2);
                mma_fp16(sc[j], ql[kt], kh2);
            }
        }

        // ---- mask, online softmax (log2-domain); overwrite sc with P ----
        const char* mbuf = smem + A_MSK + buf * 256;
#pragma unroll
        for (int j = 0; j < 8; ++j) {
            const float2 ma = *(const float2*)(mbuf + (j * 8 + 2 * tig) * 4);
            sc[j][0] += ma.x; sc[j][1] += ma.y;
            sc[j][2] += ma.x; sc[j][3] += ma.y;
        }
        float rm0 = -1e30f, rm1 = -1e30f;
#pragma unroll
        for (int j = 0; j < 8; ++j) {
            rm0 = fmaxf(rm0, fmaxf(sc[j][0], sc[j][1]));
            rm1 = fmaxf(rm1, fmaxf(sc[j][2], sc[j][3]));
        }
        rm0 = fmaxf(rm0, __shfl_xor_sync(0xFFFFFFFF, rm0, 1));
        rm0 = fmaxf(rm0, __shfl_xor_sync(0xFFFFFFFF, rm0, 2));
        rm1 = fmaxf(rm1, __shfl_xor_sync(0xFFFFFFFF, rm1, 1));
        rm1 = fmaxf(rm1, __shfl_xor_sync(0xFFFFFFFF, rm1, 2));
        const float nm0 = fmaxf(m0, rm0), nm1 = fmaxf(m1, rm1);
        const float c0 = ex2(m0 - nm0), c1 = ex2(m1 - nm1);
        m0 = nm0; m1 = nm1;
        l0 *= c0; l1 *= c1;
#pragma unroll
        for (int j = 0; j < 8; ++j) {
            o[j][0] *= c0; o[j][1] *= c0;
            o[j][2] *= c1; o[j][3] *= c1;
        }
        float s0 = 0.0f, s1 = 0.0f;
#pragma unroll
        for (int j = 0; j < 8; ++j) {
            const float p0 = ex2(sc[j][0] - nm0);
            const float p1 = ex2(sc[j][1] - nm0);
            const float p2 = ex2(sc[j][2] - nm1);
            const float p3 = ex2(sc[j][3] - nm1);
            s0 += p0 + p1; s1 += p2 + p3;
            sc[j][0] = p0; sc[j][1] = p1; sc[j][2] = p2; sc[j][3] = p3;
        }
        l0 += s0; l1 += s1;

        // ---- O += P V (fp16 k16; P direct from registers) ----
#pragma unroll
        for (int kk = 0; kk < 4; ++kk) {
            uint32_t pa[4];
            pa[0] = pack_f16x2(sc[2 * kk][0], sc[2 * kk][1]);
            pa[1] = pack_f16x2(sc[2 * kk][2], sc[2 * kk][3]);
            pa[2] = pack_f16x2(sc[2 * kk + 1][0], sc[2 * kk + 1][1]);
            pa[3] = pack_f16x2(sc[2 * kk + 1][2], sc[2 * kk + 1][3]);
#pragma unroll
            for (int j = 0; j < 8; ++j) {
                uint32_t bvf[2];
                const uint2 bv2 = *(const uint2*)(vb +
                    (((kk * 8 + j) * 32 + (lane ^ j)) << 3));
                bvf[0] = bv2.x; bvf[1] = bv2.y;
                mma_fp16(o[j], pa, bvf);
            }
        }
    }

    // ---- finalize ----
    float lt0 = l0, lt1 = l1;
    lt0 += __shfl_xor_sync(0xFFFFFFFF, lt0, 1);
    lt0 += __shfl_xor_sync(0xFFFFFFFF, lt0, 2);
    lt1 += __shfl_xor_sync(0xFFFFFFFF, lt1, 1);
    lt1 += __shfl_xor_sync(0xFFFFFFFF, lt1, 2);
    const float inv0 = 1.0f / lt0, inv1 = 1.0f / lt1;

    const int r0 = qs_base + gid, r1 = r0 + 8;
    float* o0 = g_ctx + ((size_t)(b * SS + r0)) * DD + h * DK;
    float* o1 = g_ctx + ((size_t)(b * SS + r1)) * DD + h * DK;
#pragma unroll
    for (int j = 0; j < 8; ++j) {
        const int cb = j * 8 + 2 * tig;
        float2 v0 = {o[j][0] * inv0, o[j][1] * inv0};
        float2 v1 = {o[j][2] * inv1, o[j][3] * inv1};
        *(float2*)(o0 + cb) = v0;
        *(float2*)(o1 + cb) = v1;
    }
}

// ---------------------------------------------------------------------------
// Inputs (metadata order): x, mask, Wq, bq, Wk, bk, Wv, bv, Wo, bo
// ---------------------------------------------------------------------------
extern "C" void kernel_launch(void* const* d_in, const int* in_sizes, int n_in,
                              void* d_out, int out_size) {
    const float* x  = (const float*)d_in[0];
    const int*   mk = (const int*)d_in[1];
    const float* Wq = (const float*)d_in[2];
    const float* bq = (const float*)d_in[3];
    const float* Wk = (const float*)d_in[4];
    const float* bk = (const float*)d_in[5];
    const float* Wv = (const float*)d_in[6];
    const float* bv = (const float*)d_in[7];
    const float* Wo = (const float*)d_in[8];
    const float* bo = (const float*)d_in[9];
    float* out = (float*)d_out;

    static bool configured = false;
    if (!configured) {
        cudaFuncSetAttribute(qkv_mm_kernel,
                             cudaFuncAttributeMaxDynamicSharedMemorySize,
                             MM_SMEM_BYTES);
        cudaFuncSetAttribute(oproj_mm_kernel,
                             cudaFuncAttributeMaxDynamicSharedMemorySize,
                             MM_SMEM_BYTES);
        cudaFuncSetAttribute(attn_kernel,
                             cudaFuncAttributeMaxDynamicSharedMemorySize,
                             ATTN_SMEM);
        configured = true;
    }

    // QKV projections (fp16 mma.sync); K/V written pre-packed for attention
    qkv_mm_kernel<<<dim3(DD / 128, MM / 128, 3), 256, MM_SMEM_BYTES>>>(
        x, Wq, bq, Wk, bk, Wv, bv);

    // Tensor-core flash attention (fp16 2-term QK, cp.async staging)
    attn_kernel<<<dim3(SS / 128, BB * HH), 256, ATTN_SMEM>>>(mk);

    // Output projection (fp16 mma.sync) -> d_out
    oproj_mm_kernel<<<dim3(DD / 128, MM / 128), 256, MM_SMEM_BYTES>>>(Wo, bo, out);
}